// round 14
// baseline (speedup 1.0000x reference)
#include <cuda_runtime.h>
#include <cuda_bf16.h>
#include <cuda_fp16.h>
#include <math.h>
#include <stdint.h>

// Problem constants
#define B_SZ 512
#define T_SZ 64
#define I_SZ 64
#define H_SZ 128
#define G_SZ 384   // 3*H

// ---------------- device scratch (no allocations allowed) ----------------
__device__ uint32_t g_P [I_SZ * 24576];             // per-feature W_hh, fp16 paired-fragment layout
__device__ float g_hs[B_SZ * I_SZ * H_SZ];          // GRU final hidden
__device__ float g_A [B_SZ * I_SZ * H_SZ];          // xT
__device__ float g_Wt[7 * H_SZ * H_SZ];             // transposed tail weights
__device__ int   g_rep[I_SZ];                        // adj row-dedup: rep[i] = first identical row

__device__ __forceinline__ void mma_f16(float* d, const uint32_t* a, uint32_t b0, uint32_t b1) {
    asm volatile(
        "mma.sync.aligned.m16n8k16.row.col.f32.f16.f16.f32 "
        "{%0,%1,%2,%3}, {%4,%5,%6,%7}, {%8,%9}, {%0,%1,%2,%3};"
        : "+f"(d[0]), "+f"(d[1]), "+f"(d[2]), "+f"(d[3])
        : "r"(a[0]), "r"(a[1]), "r"(a[2]), "r"(a[3]), "r"(b0), "r"(b1));
}

__device__ __forceinline__ __half2 tanh2(__half2 v) {
    uint32_t o, in = *reinterpret_cast<uint32_t*>(&v);
    asm("tanh.approx.f16x2 %0, %1;" : "=r"(o) : "r"(in));
    return *reinterpret_cast<__half2*>(&o);
}

__device__ __forceinline__ __half2 cvt2(float a, float b) {
    __half2 h;
    asm("cvt.rn.f16x2.f32 %0, %1, %2;" : "=r"(*(uint32_t*)&h) : "f"(b), "f"(a));
    return h;
}

// ---------------- pack W_hh: fp16, nA-paired B-fragment layout, r/z rows pre-scaled 0.5 ----------------
__global__ void pack_whh_kernel(const float* __restrict__ W_hh, uint32_t* __restrict__ P)
{
    int idx = blockIdx.x * blockDim.x + threadIdx.x;
    if (idx >= I_SZ * 24576) return;
    int i = idx / 24576;
    int r = idx % 24576;
    int w  = r / 3072; r %= 3072;
    int g3 = r / 1024; r %= 1024;
    int kt = r / 128;  r %= 128;
    int lane = r >> 2;
    int s = r & 3;
    int nA = s >> 1, reg = s & 1;
    int k0 = 16 * kt + 8 * reg + 2 * (lane & 3);
    int j  = 16 * w + 8 * nA + (lane >> 2);
    float scale = (g3 < 2) ? 0.5f : 1.0f;
    const float* src = W_hh + ((size_t)i * G_SZ + g3 * 128 + j) * H_SZ + k0;
    __half2 h2 = __floats2half2_rn(scale * src[0], scale * src[1]);
    P[idx] = *reinterpret_cast<uint32_t*>(&h2);
}

// ---------------- transpose x: xT[t][i][b] = x[b][t][i] ----------------
__global__ void xt_kernel(const float* __restrict__ x, float* __restrict__ xT)
{
    int idx = blockIdx.x * blockDim.x + threadIdx.x;
    if (idx >= B_SZ * T_SZ * I_SZ) return;
    int b = idx & 511;
    int r = idx >> 9;
    int i = r & 63;
    int t = r >> 6;
    xT[idx] = x[((size_t)b * T_SZ + t) * I_SZ + i];
}

// ---------------- transpose the 7 [H,H] weight matrices ----------------
__global__ void transpose7_kernel(const float* __restrict__ fp, const float* __restrict__ g1,
                                  const float* __restrict__ g2, const float* __restrict__ wk,
                                  const float* __restrict__ wv, const float* __restrict__ wq,
                                  const float* __restrict__ o0, float* __restrict__ out)
{
    int idx = blockIdx.x * blockDim.x + threadIdx.x;
    if (idx >= 7 * H_SZ * H_SZ) return;
    int w = idx >> 14;
    int r = idx & 16383;
    int k = r >> 7, n = r & 127;
    const float* src = (w == 0) ? fp : (w == 1) ? g1 : (w == 2) ? g2 :
                       (w == 3) ? wk : (w == 4) ? wv : (w == 5) ? wq : o0;
    out[idx] = src[n * 128 + k];
}

// ---------------- adj row dedup: rep[i] = first j with identical row ----------------
__global__ void rep_kernel(const float* __restrict__ adj, int* __restrict__ rep)
{
    int i = threadIdx.x;
    if (i >= I_SZ) return;
    int r = i;
    for (int j = 0; j < i; j++) {
        bool eq = true;
        for (int k = 0; k < I_SZ; k++)
            if (adj[i * I_SZ + k] != adj[j * I_SZ + k]) { eq = false; break; }
        if (eq) { r = j; break; }
    }
    rep[i] = r;
}

// ---------------- GRU scan: R13 (M=32, grid 1024, half2 epilogue) ----------------
#define GRU_SMEM_W 98304
#define GRU_SMEM   (GRU_SMEM_W + 2 * 8192)

__global__ __launch_bounds__(256, 2) void gru_kernel(
    const float* __restrict__ xT,     // [T][I][B]
    const uint32_t* __restrict__ P,
    const float* __restrict__ W_ih,   // [I][3H]
    const float* __restrict__ b_ih,
    const float* __restrict__ b_hh,
    float* __restrict__ hs_out)       // [B][I][H]
{
    extern __shared__ char smem[];
    uint4* s_B  = (uint4*)smem;
    uint4* s_A0 = (uint4*)(smem + GRU_SMEM_W);
    uint4* s_A1 = (uint4*)(smem + GRU_SMEM_W + 8192);

    const int i   = blockIdx.y;
    const int b0  = blockIdx.x * 32;
    const int tid = threadIdx.x;
    const int w    = tid >> 5;
    const int lane = tid & 31;
    const int g    = lane >> 2;
    const int t4   = lane & 3;

    // ---- stage W image (96KB) ----
    {
        const uint4* src = (const uint4*)(P + (size_t)i * 24576);
        for (int idx = tid; idx < 6144; idx += 256) s_B[idx] = src[idx];
    }

    // ---- per-thread gate constants as half2 over dj (q = nA in {0,1}), r/z scaled by 0.5 ----
    __half2 wr2[2], wz2[2], wn2[2], bin2[2], ccr2[2], ccz2[2], bhn2[2];
#pragma unroll
    for (int q = 0; q < 2; q++) {
        const int j = 16 * w + 8 * q + 2 * t4;
        const int base = i * G_SZ + j;
        wr2[q]  = __floats2half2_rn(0.5f * __ldg(&W_ih[base]),       0.5f * __ldg(&W_ih[base + 1]));
        wz2[q]  = __floats2half2_rn(0.5f * __ldg(&W_ih[base + 128]), 0.5f * __ldg(&W_ih[base + 129]));
        wn2[q]  = __floats2half2_rn(__ldg(&W_ih[base + 256]),        __ldg(&W_ih[base + 257]));
        ccr2[q] = __floats2half2_rn(0.5f * (__ldg(&b_ih[base])       + __ldg(&b_hh[base])),
                                    0.5f * (__ldg(&b_ih[base + 1])   + __ldg(&b_hh[base + 1])));
        ccz2[q] = __floats2half2_rn(0.5f * (__ldg(&b_ih[base + 128]) + __ldg(&b_hh[base + 128])),
                                    0.5f * (__ldg(&b_ih[base + 129]) + __ldg(&b_hh[base + 129])));
        bin2[q] = __floats2half2_rn(__ldg(&b_ih[base + 256]), __ldg(&b_ih[base + 257]));
        bhn2[q] = __floats2half2_rn(__ldg(&b_hh[base + 256]), __ldg(&b_hh[base + 257]));
    }

    __half2 hq[2][2][2];
    const __half2 hhalf = __float2half2_rn(0.5f);
#pragma unroll
    for (int mt = 0; mt < 2; mt++)
#pragma unroll
        for (int q = 0; q < 2; q++)
            hq[mt][q][0] = hq[mt][q][1] = __float2half2_rn(0.0f);

    __syncthreads();

    const float* xrow = xT + (size_t)i * B_SZ + b0;

    for (int t = 0; t < T_SZ; t++) {
        uint4* sA = (t & 1) ? s_A1 : s_A0;

        if (t > 0) {
#pragma unroll
            for (int mt = 0; mt < 2; mt++) {
                uint4 v;
                v.x = *reinterpret_cast<uint32_t*>(&hq[mt][0][0]);
                v.y = *reinterpret_cast<uint32_t*>(&hq[mt][0][1]);
                v.z = *reinterpret_cast<uint32_t*>(&hq[mt][1][0]);
                v.w = *reinterpret_cast<uint32_t*>(&hq[mt][1][1]);
                sA[(w * 2 + mt) * 32 + lane] = v;
            }
        }
        __syncthreads();

        __half2 x2[2][2];
#pragma unroll
        for (int mt = 0; mt < 2; mt++)
#pragma unroll
            for (int hi = 0; hi < 2; hi++)
                x2[mt][hi] = __float2half2_rn(__ldg(xrow + 16 * mt + g + 8 * hi));
        xrow += I_SZ * B_SZ;

        float D[2][6][4];
#pragma unroll
        for (int mt = 0; mt < 2; mt++)
#pragma unroll
            for (int n = 0; n < 6; n++)
#pragma unroll
                for (int c = 0; c < 4; c++) D[mt][n][c] = 0.0f;

        if (t > 0) {
#pragma unroll
            for (int kt = 0; kt < 8; kt++) {
                uint4 a0 = sA[(kt * 2 + 0) * 32 + lane];
                uint4 a1 = sA[(kt * 2 + 1) * 32 + lane];
                uint32_t af0[4] = {a0.x, a0.y, a0.z, a0.w};
                uint32_t af1[4] = {a1.x, a1.y, a1.z, a1.w};
#pragma unroll
                for (int g3 = 0; g3 < 3; g3++) {
                    uint4 bv = s_B[((w * 3 + g3) * 8 + kt) * 32 + lane];
                    mma_f16(D[0][2 * g3 + 0], af0, bv.x, bv.y);
                    mma_f16(D[0][2 * g3 + 1], af0, bv.z, bv.w);
                    mma_f16(D[1][2 * g3 + 0], af1, bv.x, bv.y);
                    mma_f16(D[1][2 * g3 + 1], af1, bv.z, bv.w);
                }
            }
        }

#pragma unroll
        for (int mt = 0; mt < 2; mt++) {
#pragma unroll
            for (int hi = 0; hi < 2; hi++) {
                const __half2 xt2 = x2[mt][hi];
                const int c0 = 2 * hi, c1 = 2 * hi + 1;
#pragma unroll
                for (int q = 0; q < 2; q++) {
                    __half2 ur2 = __hadd2(cvt2(D[mt][q][c0], D[mt][q][c1]), ccr2[q]);
                    ur2 = __hfma2(xt2, wr2[q], ur2);
                    const __half2 r2 = __hfma2(tanh2(ur2), hhalf, hhalf);
                    __half2 uz2 = __hadd2(cvt2(D[mt][2 + q][c0], D[mt][2 + q][c1]), ccz2[q]);
                    uz2 = __hfma2(xt2, wz2[q], uz2);
                    const __half2 z2 = __hfma2(tanh2(uz2), hhalf, hhalf);
                    const __half2 inn2 = __hfma2(xt2, wn2[q], bin2[q]);
                    const __half2 hn2  = __hadd2(cvt2(D[mt][4 + q][c0], D[mt][4 + q][c1]), bhn2[q]);
                    const __half2 th2  = tanh2(__hfma2(r2, hn2, inn2));
                    const __half2 hold = hq[mt][q][hi];
                    hq[mt][q][hi] = __hfma2(z2, __hsub2(hold, th2), th2);
                }
            }
        }
    }

#pragma unroll
    for (int mt = 0; mt < 2; mt++)
#pragma unroll
        for (int q = 0; q < 2; q++) {
            const int j = 16 * w + 8 * q + 2 * t4;
#pragma unroll
            for (int hi = 0; hi < 2; hi++) {
                const int b = b0 + 16 * mt + g + 8 * hi;
                float2 f = __half22float2(hq[mt][q][hi]);
                *(float2*)(hs_out + ((size_t)b * I_SZ + i) * H_SZ + j) = f;
            }
        }
}

// ---------------- fused tail helpers ----------------
__device__ __forceinline__ void lin_smem(const float* __restrict__ Xin, const float* __restrict__ Wt,
                                         const float* __restrict__ bias, float* __restrict__ Yout,
                                         float* __restrict__ gout, int relu, int w, int l)
{
    const int r0 = w * 8;
    float acc[8][4];
#pragma unroll
    for (int rr = 0; rr < 8; rr++)
#pragma unroll
        for (int c = 0; c < 4; c++) acc[rr][c] = 0.f;
#pragma unroll 4
    for (int k = 0; k < 128; k++) {
        float wv[4];
#pragma unroll
        for (int c = 0; c < 4; c++) wv[c] = __ldg(&Wt[k * 128 + l + 32 * c]);
#pragma unroll
        for (int rr = 0; rr < 8; rr++) {
            const float xv = Xin[(r0 + rr) * 128 + k];
#pragma unroll
            for (int c = 0; c < 4; c++) acc[rr][c] = fmaf(xv, wv[c], acc[rr][c]);
        }
    }
#pragma unroll
    for (int rr = 0; rr < 8; rr++)
#pragma unroll
        for (int c = 0; c < 4; c++) {
            const int n = l + 32 * c;
            float v = acc[rr][c] + __ldg(&bias[n]);
            if (relu) v = fmaxf(v, 0.f);
            Yout[(rr + r0) * 128 + n] = v;
            if (gout) gout[(size_t)(r0 + rr) * 128 + n] = v;
        }
}

// adj @ X with row dedup: compute only representative rows (phase 1)
__device__ __forceinline__ void adj_rep_compute(const float* __restrict__ Xin, const float* __restrict__ adj,
                                                const int* __restrict__ srep, float* __restrict__ Yout,
                                                int w, int l)
{
    const int i0 = w * 8;
    for (int ii = 0; ii < 8; ii++) {
        const int row = i0 + ii;
        if (srep[row] != row) continue;   // non-representative: copied in phase 2
        float acc[4] = {0.f, 0.f, 0.f, 0.f};
#pragma unroll 4
        for (int j = 0; j < 64; j++) {
            const float a = __ldg(&adj[row * 64 + j]);
#pragma unroll
            for (int c = 0; c < 4; c++) acc[c] = fmaf(a, Xin[j * 128 + l + 32 * c], acc[c]);
        }
#pragma unroll
        for (int c = 0; c < 4; c++)
            Yout[row * 128 + l + 32 * c] = acc[c];
    }
}

// phase 2: duplicate rows (bit-identical copies)
__device__ __forceinline__ void adj_rep_copy(const int* __restrict__ srep, float* __restrict__ Yout,
                                             int w, int l)
{
    const int i0 = w * 8;
    for (int ii = 0; ii < 8; ii++) {
        const int row = i0 + ii;
        const int rp = srep[row];
        if (rp == row) continue;
#pragma unroll
        for (int c = 0; c < 4; c++)
            Yout[row * 128 + l + 32 * c] = Yout[rp * 128 + l + 32 * c];
    }
}

// one block per batch: hs -> ht(out) -> adj -> g1 -> adj -> g2 -> attention -> out
#define TAIL_SMEM (16384 * 4 + 4 * (128 * 4 + 64 + 2) + 256)

__global__ __launch_bounds__(256) void tail_kernel(
    const float* __restrict__ hs, const float* __restrict__ adj, const int* __restrict__ rep,
    const float* __restrict__ fpT, const float* __restrict__ fp_b,
    const float* __restrict__ g1T, const float* __restrict__ g1_b,
    const float* __restrict__ g2T, const float* __restrict__ g2_b,
    const float* __restrict__ wqT, const float* __restrict__ wq_b,
    const float* __restrict__ wk_w, const float* __restrict__ wk_b,
    const float* __restrict__ wvT, const float* __restrict__ wv_b,
    const float* __restrict__ o0T, const float* __restrict__ o0_b,
    float* __restrict__ ht_out, float* __restrict__ out)
{
    extern __shared__ float sm[];
    float* Xs = sm;                  // [64][128]
    float* Zs = sm + 8192;           // [64][128]
    float* q  = sm + 16384;
    float* u  = q + 128;
    float* s  = u + 128;
    float* wc = s + 128;
    float* ev = wc + 128;
    float* red = ev + 64;
    __shared__ int srep[64];

    const int b = blockIdx.x;
    const int tid = threadIdx.x, w = tid >> 5, l = tid & 31;

    for (int idx = tid; idx < 8192; idx += 256)
        Xs[idx] = hs[(size_t)b * 8192 + idx];
    if (tid < 64) srep[tid] = rep[tid];
    __syncthreads();

    // ht = hs @ fpT + fp_b (also to d_out)
    lin_smem(Xs, fpT, fp_b, Zs, ht_out + (size_t)b * 8192, 0, w, l);
    __syncthreads();
    // adj @ ht (dedup)
    adj_rep_compute(Zs, adj, srep, Xs, w, l);
    __syncthreads();
    adj_rep_copy(srep, Xs, w, l);
    __syncthreads();
    lin_smem(Xs, g1T, g1_b, Zs, nullptr, 1, w, l);
    __syncthreads();
    // adj @ g (dedup)
    adj_rep_compute(Zs, adj, srep, Xs, w, l);
    __syncthreads();
    adj_rep_copy(srep, Xs, w, l);
    __syncthreads();
    lin_smem(Xs, g2T, g2_b, Zs, nullptr, 1, w, l);   // Zs = ctx
    __syncthreads();

    // ---- attention on ctx (Zs) ----
    if (tid < 128) {
        float acc = __ldg(&wq_b[tid]);
        for (int k = 0; k < 128; k++)
            acc = fmaf(Zs[63 * 128 + k], __ldg(&wqT[k * 128 + tid]), acc);
        q[tid] = acc;
    }
    __syncthreads();
    if (tid < 128) {
        float acc = 0.f;
        for (int n = 0; n < 128; n++)
            acc = fmaf(q[n], __ldg(&wk_w[n * 128 + tid]), acc);
        u[tid] = acc;
    }
    if (tid == 128) {
        float c = 0.f;
        for (int n = 0; n < 128; n++) c = fmaf(q[n], __ldg(&wk_b[n]), c);
        red[0] = c;
    }
    __syncthreads();
    if (tid < 64) {
        float e = red[0];
        for (int k = 0; k < 128; k++) e = fmaf(Zs[tid * 128 + k], u[k], e);
        ev[tid] = e;
    }
    __syncthreads();
    if (tid == 0) {
        float mx = -1e30f;
        for (int ii = 0; ii < 64; ii++) mx = fmaxf(mx, ev[ii]);
        float smm = 0.f;
        for (int ii = 0; ii < 64; ii++) smm += __expf(ev[ii] - mx);
        red[0] = mx; red[1] = 1.0f / smm;
    }
    __syncthreads();
    if (tid < 64) ev[tid] = __expf(ev[tid] - red[0]) * red[1];
    __syncthreads();
    if (tid < 128) {
        float acc = 0.f;
        for (int ii = 0; ii < 64; ii++) acc = fmaf(ev[ii], Zs[ii * 128 + tid], acc);
        s[tid] = acc;
    }
    __syncthreads();
    if (tid < 128) {
        float acc = __ldg(&wv_b[tid]);
        for (int k = 0; k < 128; k++) acc = fmaf(s[k], __ldg(&wvT[k * 128 + tid]), acc);
        wc[tid] = acc;
    }
    __syncthreads();
    if (tid < 128) {
        float acc = __ldg(&o0_b[tid]);
        for (int m = 0; m < 128; m++) acc = fmaf(wc[m], __ldg(&o0T[m * 128 + tid]), acc);
        out[(size_t)b * 128 + tid] = fmaxf(acc, 0.f);
    }
}

// ---------------- launch ----------------
extern "C" void kernel_launch(void* const* d_in, const int* in_sizes, int n_in,
                              void* d_out, int out_size)
{
    const float* x     = (const float*)d_in[0];
    const float* W_ih  = (const float*)d_in[1];
    const float* W_hh  = (const float*)d_in[2];
    const float* b_ih  = (const float*)d_in[3];
    const float* b_hh  = (const float*)d_in[4];
    const float* fp_w  = (const float*)d_in[5];
    const float* fp_b  = (const float*)d_in[6];
    const float* g1_w  = (const float*)d_in[7];
    const float* g1_b  = (const float*)d_in[8];
    const float* g2_w  = (const float*)d_in[9];
    const float* g2_b  = (const float*)d_in[10];
    const float* wq_w  = (const float*)d_in[11];
    const float* wq_b  = (const float*)d_in[12];
    const float* wk_w  = (const float*)d_in[13];
    const float* wk_b  = (const float*)d_in[14];
    const float* wv_w  = (const float*)d_in[15];
    const float* wv_b  = (const float*)d_in[16];
    const float* o0_w  = (const float*)d_in[17];
    const float* o0_b  = (const float*)d_in[18];
    const float* adj   = (const float*)d_in[19];

    float* out = (float*)d_out;
    float* ht_out = out + B_SZ * H_SZ;

    uint32_t* P;
    float *hs, *A, *Wt;
    int* rep;
    cudaGetSymbolAddress((void**)&P,  g_P);
    cudaGetSymbolAddress((void**)&hs, g_hs);
    cudaGetSymbolAddress((void**)&A,  g_A);
    cudaGetSymbolAddress((void**)&Wt, g_Wt);
    cudaGetSymbolAddress((void**)&rep, g_rep);

    cudaFuncSetAttribute(gru_kernel, cudaFuncAttributeMaxDynamicSharedMemorySize, GRU_SMEM);
    cudaFuncSetAttribute(tail_kernel, cudaFuncAttributeMaxDynamicSharedMemorySize, TAIL_SMEM);

    // prep
    pack_whh_kernel<<<(I_SZ * 24576 + 255) / 256, 256>>>(W_hh, P);
    transpose7_kernel<<<(7 * H_SZ * H_SZ + 255) / 256, 256>>>(fp_w, g1_w, g2_w, wk_w, wv_w, wq_w, o0_w, Wt);
    xt_kernel<<<(B_SZ * T_SZ * I_SZ + 255) / 256, 256>>>(x, A);
    rep_kernel<<<1, 64>>>(adj, rep);

    const float* fpT = Wt + 0 * 16384;
    const float* g1T = Wt + 1 * 16384;
    const float* g2T = Wt + 2 * 16384;
    const float* wvT = Wt + 4 * 16384;
    const float* wqT = Wt + 5 * 16384;
    const float* o0T = Wt + 6 * 16384;

    // 1) GRU scan -> hs (M=32 per CTA, 1024 CTAs)
    gru_kernel<<<dim3(16, 64), 256, GRU_SMEM>>>(A, P, W_ih, b_ih, b_hh, hs);

    // 2) fused tail (adj row-dedup)
    tail_kernel<<<B_SZ, 256, TAIL_SMEM>>>(hs, adj, rep,
                                          fpT, fp_b, g1T, g1_b, g2T, g2_b,
                                          wqT, wq_b, wk_w, wk_b, wvT, wv_b,
                                          o0T, o0_b, ht_out, out);
}

// round 15
// speedup vs baseline: 1.0499x; 1.0499x over previous
#include <cuda_runtime.h>
#include <cuda_bf16.h>
#include <cuda_fp16.h>
#include <math.h>
#include <stdint.h>

// Problem constants
#define B_SZ 512
#define T_SZ 64
#define I_SZ 64
#define H_SZ 128
#define G_SZ 384   // 3*H

// ---------------- device scratch (no allocations allowed) ----------------
__device__ uint32_t g_P [I_SZ * 24576];             // per-feature W_hh, fp16 paired-fragment layout
__device__ float g_hs[B_SZ * I_SZ * H_SZ];          // GRU final hidden
__device__ float g_A [B_SZ * I_SZ * H_SZ];          // xT
__device__ float g_Wt[7 * H_SZ * H_SZ];             // transposed tail weights
__device__ int   g_rep[I_SZ];                        // adj row-dedup: rep[i] = first identical row

__device__ __forceinline__ void mma_f16(float* d, const uint32_t* a, uint32_t b0, uint32_t b1) {
    asm volatile(
        "mma.sync.aligned.m16n8k16.row.col.f32.f16.f16.f32 "
        "{%0,%1,%2,%3}, {%4,%5,%6,%7}, {%8,%9}, {%0,%1,%2,%3};"
        : "+f"(d[0]), "+f"(d[1]), "+f"(d[2]), "+f"(d[3])
        : "r"(a[0]), "r"(a[1]), "r"(a[2]), "r"(a[3]), "r"(b0), "r"(b1));
}

__device__ __forceinline__ __half2 tanh2(__half2 v) {
    uint32_t o, in = *reinterpret_cast<uint32_t*>(&v);
    asm("tanh.approx.f16x2 %0, %1;" : "=r"(o) : "r"(in));
    return *reinterpret_cast<__half2*>(&o);
}

__device__ __forceinline__ __half2 cvt2(float a, float b) {
    __half2 h;
    asm("cvt.rn.f16x2.f32 %0, %1, %2;" : "=r"(*(uint32_t*)&h) : "f"(b), "f"(a));
    return h;
}

// ---------------- pack W_hh: fp16, nA-paired B-fragment layout, r/z rows pre-scaled 0.5 ----------------
__global__ void pack_whh_kernel(const float* __restrict__ W_hh, uint32_t* __restrict__ P)
{
    int idx = blockIdx.x * blockDim.x + threadIdx.x;
    if (idx >= I_SZ * 24576) return;
    int i = idx / 24576;
    int r = idx % 24576;
    int w  = r / 3072; r %= 3072;
    int g3 = r / 1024; r %= 1024;
    int kt = r / 128;  r %= 128;
    int lane = r >> 2;
    int s = r & 3;
    int nA = s >> 1, reg = s & 1;
    int k0 = 16 * kt + 8 * reg + 2 * (lane & 3);
    int j  = 16 * w + 8 * nA + (lane >> 2);
    float scale = (g3 < 2) ? 0.5f : 1.0f;
    const float* src = W_hh + ((size_t)i * G_SZ + g3 * 128 + j) * H_SZ + k0;
    __half2 h2 = __floats2half2_rn(scale * src[0], scale * src[1]);
    P[idx] = *reinterpret_cast<uint32_t*>(&h2);
}

// ---------------- transpose x: xT[t][i][b] = x[b][t][i] ----------------
__global__ void xt_kernel(const float* __restrict__ x, float* __restrict__ xT)
{
    int idx = blockIdx.x * blockDim.x + threadIdx.x;
    if (idx >= B_SZ * T_SZ * I_SZ) return;
    int b = idx & 511;
    int r = idx >> 9;
    int i = r & 63;
    int t = r >> 6;
    xT[idx] = x[((size_t)b * T_SZ + t) * I_SZ + i];
}

// ---------------- transpose the 7 [H,H] weight matrices ----------------
__global__ void transpose7_kernel(const float* __restrict__ fp, const float* __restrict__ g1,
                                  const float* __restrict__ g2, const float* __restrict__ wk,
                                  const float* __restrict__ wv, const float* __restrict__ wq,
                                  const float* __restrict__ o0, float* __restrict__ out)
{
    int idx = blockIdx.x * blockDim.x + threadIdx.x;
    if (idx >= 7 * H_SZ * H_SZ) return;
    int w = idx >> 14;
    int r = idx & 16383;
    int k = r >> 7, n = r & 127;
    const float* src = (w == 0) ? fp : (w == 1) ? g1 : (w == 2) ? g2 :
                       (w == 3) ? wk : (w == 4) ? wv : (w == 5) ? wq : o0;
    out[idx] = src[n * 128 + k];
}

// ---------------- adj row dedup (parallel): grid 64 x block 64 ----------------
__global__ void rep_kernel(const float* __restrict__ adj, int* __restrict__ rep)
{
    __shared__ int best;
    const int i = blockIdx.x, j = threadIdx.x;
    if (j == 0) best = i;
    __syncthreads();
    if (j < i) {
        bool eq = true;
        for (int k = 0; k < I_SZ; k++)
            if (adj[i * I_SZ + k] != adj[j * I_SZ + k]) { eq = false; break; }
        if (eq) atomicMin(&best, j);
    }
    __syncthreads();
    if (j == 0) rep[i] = best;
}

// ---------------- GRU scan: R13 (M=32, grid 1024, half2 epilogue) ----------------
#define GRU_SMEM_W 98304
#define GRU_SMEM   (GRU_SMEM_W + 2 * 8192)

__global__ __launch_bounds__(256, 2) void gru_kernel(
    const float* __restrict__ xT,     // [T][I][B]
    const uint32_t* __restrict__ P,
    const float* __restrict__ W_ih,   // [I][3H]
    const float* __restrict__ b_ih,
    const float* __restrict__ b_hh,
    float* __restrict__ hs_out)       // [B][I][H]
{
    extern __shared__ char smem[];
    uint4* s_B  = (uint4*)smem;
    uint4* s_A0 = (uint4*)(smem + GRU_SMEM_W);
    uint4* s_A1 = (uint4*)(smem + GRU_SMEM_W + 8192);

    const int i   = blockIdx.y;
    const int b0  = blockIdx.x * 32;
    const int tid = threadIdx.x;
    const int w    = tid >> 5;
    const int lane = tid & 31;
    const int g    = lane >> 2;
    const int t4   = lane & 3;

    {
        const uint4* src = (const uint4*)(P + (size_t)i * 24576);
        for (int idx = tid; idx < 6144; idx += 256) s_B[idx] = src[idx];
    }

    __half2 wr2[2], wz2[2], wn2[2], bin2[2], ccr2[2], ccz2[2], bhn2[2];
#pragma unroll
    for (int q = 0; q < 2; q++) {
        const int j = 16 * w + 8 * q + 2 * t4;
        const int base = i * G_SZ + j;
        wr2[q]  = __floats2half2_rn(0.5f * __ldg(&W_ih[base]),       0.5f * __ldg(&W_ih[base + 1]));
        wz2[q]  = __floats2half2_rn(0.5f * __ldg(&W_ih[base + 128]), 0.5f * __ldg(&W_ih[base + 129]));
        wn2[q]  = __floats2half2_rn(__ldg(&W_ih[base + 256]),        __ldg(&W_ih[base + 257]));
        ccr2[q] = __floats2half2_rn(0.5f * (__ldg(&b_ih[base])       + __ldg(&b_hh[base])),
                                    0.5f * (__ldg(&b_ih[base + 1])   + __ldg(&b_hh[base + 1])));
        ccz2[q] = __floats2half2_rn(0.5f * (__ldg(&b_ih[base + 128]) + __ldg(&b_hh[base + 128])),
                                    0.5f * (__ldg(&b_ih[base + 129]) + __ldg(&b_hh[base + 129])));
        bin2[q] = __floats2half2_rn(__ldg(&b_ih[base + 256]), __ldg(&b_ih[base + 257]));
        bhn2[q] = __floats2half2_rn(__ldg(&b_hh[base + 256]), __ldg(&b_hh[base + 257]));
    }

    __half2 hq[2][2][2];
    const __half2 hhalf = __float2half2_rn(0.5f);
#pragma unroll
    for (int mt = 0; mt < 2; mt++)
#pragma unroll
        for (int q = 0; q < 2; q++)
            hq[mt][q][0] = hq[mt][q][1] = __float2half2_rn(0.0f);

    __syncthreads();

    const float* xrow = xT + (size_t)i * B_SZ + b0;

    for (int t = 0; t < T_SZ; t++) {
        uint4* sA = (t & 1) ? s_A1 : s_A0;

        if (t > 0) {
#pragma unroll
            for (int mt = 0; mt < 2; mt++) {
                uint4 v;
                v.x = *reinterpret_cast<uint32_t*>(&hq[mt][0][0]);
                v.y = *reinterpret_cast<uint32_t*>(&hq[mt][0][1]);
                v.z = *reinterpret_cast<uint32_t*>(&hq[mt][1][0]);
                v.w = *reinterpret_cast<uint32_t*>(&hq[mt][1][1]);
                sA[(w * 2 + mt) * 32 + lane] = v;
            }
        }
        __syncthreads();

        __half2 x2[2][2];
#pragma unroll
        for (int mt = 0; mt < 2; mt++)
#pragma unroll
            for (int hi = 0; hi < 2; hi++)
                x2[mt][hi] = __float2half2_rn(__ldg(xrow + 16 * mt + g + 8 * hi));
        xrow += I_SZ * B_SZ;

        float D[2][6][4];
#pragma unroll
        for (int mt = 0; mt < 2; mt++)
#pragma unroll
            for (int n = 0; n < 6; n++)
#pragma unroll
                for (int c = 0; c < 4; c++) D[mt][n][c] = 0.0f;

        if (t > 0) {
#pragma unroll
            for (int kt = 0; kt < 8; kt++) {
                uint4 a0 = sA[(kt * 2 + 0) * 32 + lane];
                uint4 a1 = sA[(kt * 2 + 1) * 32 + lane];
                uint32_t af0[4] = {a0.x, a0.y, a0.z, a0.w};
                uint32_t af1[4] = {a1.x, a1.y, a1.z, a1.w};
#pragma unroll
                for (int g3 = 0; g3 < 3; g3++) {
                    uint4 bv = s_B[((w * 3 + g3) * 8 + kt) * 32 + lane];
                    mma_f16(D[0][2 * g3 + 0], af0, bv.x, bv.y);
                    mma_f16(D[0][2 * g3 + 1], af0, bv.z, bv.w);
                    mma_f16(D[1][2 * g3 + 0], af1, bv.x, bv.y);
                    mma_f16(D[1][2 * g3 + 1], af1, bv.z, bv.w);
                }
            }
        }

#pragma unroll
        for (int mt = 0; mt < 2; mt++) {
#pragma unroll
            for (int hi = 0; hi < 2; hi++) {
                const __half2 xt2 = x2[mt][hi];
                const int c0 = 2 * hi, c1 = 2 * hi + 1;
#pragma unroll
                for (int q = 0; q < 2; q++) {
                    __half2 ur2 = __hadd2(cvt2(D[mt][q][c0], D[mt][q][c1]), ccr2[q]);
                    ur2 = __hfma2(xt2, wr2[q], ur2);
                    const __half2 r2 = __hfma2(tanh2(ur2), hhalf, hhalf);
                    __half2 uz2 = __hadd2(cvt2(D[mt][2 + q][c0], D[mt][2 + q][c1]), ccz2[q]);
                    uz2 = __hfma2(xt2, wz2[q], uz2);
                    const __half2 z2 = __hfma2(tanh2(uz2), hhalf, hhalf);
                    const __half2 inn2 = __hfma2(xt2, wn2[q], bin2[q]);
                    const __half2 hn2  = __hadd2(cvt2(D[mt][4 + q][c0], D[mt][4 + q][c1]), bhn2[q]);
                    const __half2 th2  = tanh2(__hfma2(r2, hn2, inn2));
                    const __half2 hold = hq[mt][q][hi];
                    hq[mt][q][hi] = __hfma2(z2, __hsub2(hold, th2), th2);
                }
            }
        }
    }

#pragma unroll
    for (int mt = 0; mt < 2; mt++)
#pragma unroll
        for (int q = 0; q < 2; q++) {
            const int j = 16 * w + 8 * q + 2 * t4;
#pragma unroll
            for (int hi = 0; hi < 2; hi++) {
                const int b = b0 + 16 * mt + g + 8 * hi;
                float2 f = __half22float2(hq[mt][q][hi]);
                *(float2*)(hs_out + ((size_t)b * I_SZ + i) * H_SZ + j) = f;
            }
        }
}

// ---------------- fused tail helpers ----------------
__device__ __forceinline__ void lin_smem(const float* __restrict__ Xin, const float* __restrict__ Wt,
                                         const float* __restrict__ bias, float* __restrict__ Yout,
                                         float* __restrict__ gout, int relu, int w, int l)
{
    const int r0 = w * 8;
    float acc[8][4];
#pragma unroll
    for (int rr = 0; rr < 8; rr++)
#pragma unroll
        for (int c = 0; c < 4; c++) acc[rr][c] = 0.f;
#pragma unroll 4
    for (int k = 0; k < 128; k++) {
        float wv[4];
#pragma unroll
        for (int c = 0; c < 4; c++) wv[c] = __ldg(&Wt[k * 128 + l + 32 * c]);
#pragma unroll
        for (int rr = 0; rr < 8; rr++) {
            const float xv = Xin[(r0 + rr) * 128 + k];
#pragma unroll
            for (int c = 0; c < 4; c++) acc[rr][c] = fmaf(xv, wv[c], acc[rr][c]);
        }
    }
#pragma unroll
    for (int rr = 0; rr < 8; rr++)
#pragma unroll
        for (int c = 0; c < 4; c++) {
            const int n = l + 32 * c;
            float v = acc[rr][c] + __ldg(&bias[n]);
            if (relu) v = fmaxf(v, 0.f);
            Yout[(r0 + rr) * 128 + n] = v;
            if (gout) gout[(size_t)(r0 + rr) * 128 + n] = v;
        }
}

// adj @ X via unique-row compaction: flat-parallel over nU*128 dot products, then flat copy.
__device__ __forceinline__ void adj_dedup(const float* __restrict__ Xin, const float* __restrict__ adj,
                                          const int* __restrict__ srep, const int* __restrict__ ulist,
                                          int nU, float* __restrict__ Yout, int tid)
{
    const int total = nU * 128;
    for (int item = tid; item < total; item += 256) {
        const int row = ulist[item >> 7];
        const int col = item & 127;
        float acc = 0.f;
#pragma unroll 4
        for (int j = 0; j < 64; j++)
            acc = fmaf(__ldg(&adj[row * 64 + j]), Xin[j * 128 + col], acc);
        Yout[row * 128 + col] = acc;
    }
    __syncthreads();
    for (int item = tid; item < 8192; item += 256) {
        const int row = item >> 7;
        const int rp = srep[row];
        if (rp != row) Yout[item] = Yout[rp * 128 + (item & 127)];
    }
}

// one block per batch: hs -> ht(out) -> adj -> g1 -> adj -> g2 -> attention -> out
#define TAIL_SMEM (16384 * 4 + 4 * (128 * 4 + 64 + 2) + 256)

__global__ __launch_bounds__(256) void tail_kernel(
    const float* __restrict__ hs, const float* __restrict__ adj, const int* __restrict__ rep,
    const float* __restrict__ fpT, const float* __restrict__ fp_b,
    const float* __restrict__ g1T, const float* __restrict__ g1_b,
    const float* __restrict__ g2T, const float* __restrict__ g2_b,
    const float* __restrict__ wqT, const float* __restrict__ wq_b,
    const float* __restrict__ wk_w, const float* __restrict__ wk_b,
    const float* __restrict__ wvT, const float* __restrict__ wv_b,
    const float* __restrict__ o0T, const float* __restrict__ o0_b,
    float* __restrict__ ht_out, float* __restrict__ out)
{
    extern __shared__ float sm[];
    float* Xs = sm;                  // [64][128]
    float* Zs = sm + 8192;           // [64][128]
    float* q  = sm + 16384;
    float* u  = q + 128;
    float* s  = u + 128;
    float* wc = s + 128;
    float* ev = wc + 128;
    float* red = ev + 64;
    __shared__ int srep[64], ulist[64], nU_s;

    const int b = blockIdx.x;
    const int tid = threadIdx.x, w = tid >> 5, l = tid & 31;

    for (int idx = tid; idx < 8192; idx += 256)
        Xs[idx] = hs[(size_t)b * 8192 + idx];
    if (tid < 64) srep[tid] = rep[tid];
    __syncthreads();
    if (tid == 0) {
        int n = 0;
        for (int r = 0; r < 64; r++)
            if (srep[r] == r) ulist[n++] = r;
        nU_s = n;
    }
    __syncthreads();
    const int nU = nU_s;

    // ht = hs @ fpT + fp_b (also to d_out)
    lin_smem(Xs, fpT, fp_b, Zs, ht_out + (size_t)b * 8192, 0, w, l);
    __syncthreads();
    // adj @ ht (compacted)
    adj_dedup(Zs, adj, srep, ulist, nU, Xs, tid);
    __syncthreads();
    lin_smem(Xs, g1T, g1_b, Zs, nullptr, 1, w, l);
    __syncthreads();
    // adj @ g (compacted)
    adj_dedup(Zs, adj, srep, ulist, nU, Xs, tid);
    __syncthreads();
    lin_smem(Xs, g2T, g2_b, Zs, nullptr, 1, w, l);   // Zs = ctx
    __syncthreads();

    // ---- attention on ctx (Zs) ----
    if (tid < 128) {
        float acc = __ldg(&wq_b[tid]);
        for (int k = 0; k < 128; k++)
            acc = fmaf(Zs[63 * 128 + k], __ldg(&wqT[k * 128 + tid]), acc);
        q[tid] = acc;
    }
    __syncthreads();
    if (tid < 128) {
        float acc = 0.f;
        for (int n = 0; n < 128; n++)
            acc = fmaf(q[n], __ldg(&wk_w[n * 128 + tid]), acc);
        u[tid] = acc;
    }
    if (tid == 128) {
        float c = 0.f;
        for (int n = 0; n < 128; n++) c = fmaf(q[n], __ldg(&wk_b[n]), c);
        red[0] = c;
    }
    __syncthreads();
    if (tid < 64) {
        float e = red[0];
        for (int k = 0; k < 128; k++) e = fmaf(Zs[tid * 128 + k], u[k], e);
        ev[tid] = e;
    }
    __syncthreads();
    if (tid == 0) {
        float mx = -1e30f;
        for (int ii = 0; ii < 64; ii++) mx = fmaxf(mx, ev[ii]);
        float smm = 0.f;
        for (int ii = 0; ii < 64; ii++) smm += __expf(ev[ii] - mx);
        red[0] = mx; red[1] = 1.0f / smm;
    }
    __syncthreads();
    if (tid < 64) ev[tid] = __expf(ev[tid] - red[0]) * red[1];
    __syncthreads();
    if (tid < 128) {
        float acc = 0.f;
        for (int ii = 0; ii < 64; ii++) acc = fmaf(ev[ii], Zs[ii * 128 + tid], acc);
        s[tid] = acc;
    }
    __syncthreads();
    if (tid < 128) {
        float acc = __ldg(&wv_b[tid]);
        for (int k = 0; k < 128; k++) acc = fmaf(s[k], __ldg(&wvT[k * 128 + tid]), acc);
        wc[tid] = acc;
    }
    __syncthreads();
    if (tid < 128) {
        float acc = __ldg(&o0_b[tid]);
        for (int m = 0; m < 128; m++) acc = fmaf(wc[m], __ldg(&o0T[m * 128 + tid]), acc);
        out[(size_t)b * 128 + tid] = fmaxf(acc, 0.f);
    }
}

// ---------------- launch ----------------
extern "C" void kernel_launch(void* const* d_in, const int* in_sizes, int n_in,
                              void* d_out, int out_size)
{
    const float* x     = (const float*)d_in[0];
    const float* W_ih  = (const float*)d_in[1];
    const float* W_hh  = (const float*)d_in[2];
    const float* b_ih  = (const float*)d_in[3];
    const float* b_hh  = (const float*)d_in[4];
    const float* fp_w  = (const float*)d_in[5];
    const float* fp_b  = (const float*)d_in[6];
    const float* g1_w  = (const float*)d_in[7];
    const float* g1_b  = (const float*)d_in[8];
    const float* g2_w  = (const float*)d_in[9];
    const float* g2_b  = (const float*)d_in[10];
    const float* wq_w  = (const float*)d_in[11];
    const float* wq_b  = (const float*)d_in[12];
    const float* wk_w  = (const float*)d_in[13];
    const float* wk_b  = (const float*)d_in[14];
    const float* wv_w  = (const float*)d_in[15];
    const float* wv_b  = (const float*)d_in[16];
    const float* o0_w  = (const float*)d_in[17];
    const float* o0_b  = (const float*)d_in[18];
    const float* adj   = (const float*)d_in[19];

    float* out = (float*)d_out;
    float* ht_out = out + B_SZ * H_SZ;

    uint32_t* P;
    float *hs, *A, *Wt;
    int* rep;
    cudaGetSymbolAddress((void**)&P,  g_P);
    cudaGetSymbolAddress((void**)&hs, g_hs);
    cudaGetSymbolAddress((void**)&A,  g_A);
    cudaGetSymbolAddress((void**)&Wt, g_Wt);
    cudaGetSymbolAddress((void**)&rep, g_rep);

    cudaFuncSetAttribute(gru_kernel, cudaFuncAttributeMaxDynamicSharedMemorySize, GRU_SMEM);
    cudaFuncSetAttribute(tail_kernel, cudaFuncAttributeMaxDynamicSharedMemorySize, TAIL_SMEM);

    // prep
    pack_whh_kernel<<<(I_SZ * 24576 + 255) / 256, 256>>>(W_hh, P);
    transpose7_kernel<<<(7 * H_SZ * H_SZ + 255) / 256, 256>>>(fp_w, g1_w, g2_w, wk_w, wv_w, wq_w, o0_w, Wt);
    xt_kernel<<<(B_SZ * T_SZ * I_SZ + 255) / 256, 256>>>(x, A);
    rep_kernel<<<64, 64>>>(adj, rep);

    const float* fpT = Wt + 0 * 16384;
    const float* g1T = Wt + 1 * 16384;
    const float* g2T = Wt + 2 * 16384;
    const float* wvT = Wt + 4 * 16384;
    const float* wqT = Wt + 5 * 16384;
    const float* o0T = Wt + 6 * 16384;

    // 1) GRU scan -> hs (M=32 per CTA, 1024 CTAs)
    gru_kernel<<<dim3(16, 64), 256, GRU_SMEM>>>(A, P, W_ih, b_ih, b_hh, hs);

    // 2) fused tail (compacted adj dedup)
    tail_kernel<<<B_SZ, 256, TAIL_SMEM>>>(hs, adj, rep,
                                          fpT, fp_b, g1T, g1_b, g2T, g2_b,
                                          wqT, wq_b, wk_w, wk_b, wvT, wv_b,
                                          o0T, o0_b, ht_out, out);
}

// round 16
// speedup vs baseline: 1.1187x; 1.0656x over previous
#include <cuda_runtime.h>
#include <cuda_bf16.h>
#include <cuda_fp16.h>
#include <math.h>
#include <stdint.h>

// Problem constants
#define B_SZ 512
#define T_SZ 64
#define I_SZ 64
#define H_SZ 128
#define G_SZ 384   // 3*H

// ---------------- device scratch (no allocations allowed) ----------------
__device__ uint32_t g_P [I_SZ * 24576];             // per-feature W_hh, fp16 paired-fragment layout
__device__ float g_hs[B_SZ * I_SZ * H_SZ];          // GRU final hidden
__device__ float g_A [B_SZ * I_SZ * H_SZ];          // xT
__device__ float g_Wt[7 * H_SZ * H_SZ];             // transposed tail weights
__device__ int   g_rep[I_SZ];                        // adj row-dedup: rep[i] = first identical row

__device__ __forceinline__ void mma_f16(float* d, const uint32_t* a, uint32_t b0, uint32_t b1) {
    asm volatile(
        "mma.sync.aligned.m16n8k16.row.col.f32.f16.f16.f32 "
        "{%0,%1,%2,%3}, {%4,%5,%6,%7}, {%8,%9}, {%0,%1,%2,%3};"
        : "+f"(d[0]), "+f"(d[1]), "+f"(d[2]), "+f"(d[3])
        : "r"(a[0]), "r"(a[1]), "r"(a[2]), "r"(a[3]), "r"(b0), "r"(b1));
}

__device__ __forceinline__ __half2 tanh2(__half2 v) {
    uint32_t o, in = *reinterpret_cast<uint32_t*>(&v);
    asm("tanh.approx.f16x2 %0, %1;" : "=r"(o) : "r"(in));
    return *reinterpret_cast<__half2*>(&o);
}

__device__ __forceinline__ __half2 cvt2(float a, float b) {
    __half2 h;
    asm("cvt.rn.f16x2.f32 %0, %1, %2;" : "=r"(*(uint32_t*)&h) : "f"(b), "f"(a));
    return h;
}

// ---------------- pack W_hh: fp16, nA-paired B-fragment layout, r/z rows pre-scaled 0.5 ----------------
__global__ void pack_whh_kernel(const float* __restrict__ W_hh, uint32_t* __restrict__ P)
{
    int idx = blockIdx.x * blockDim.x + threadIdx.x;
    if (idx >= I_SZ * 24576) return;
    int i = idx / 24576;
    int r = idx % 24576;
    int w  = r / 3072; r %= 3072;
    int g3 = r / 1024; r %= 1024;
    int kt = r / 128;  r %= 128;
    int lane = r >> 2;
    int s = r & 3;
    int nA = s >> 1, reg = s & 1;
    int k0 = 16 * kt + 8 * reg + 2 * (lane & 3);
    int j  = 16 * w + 8 * nA + (lane >> 2);
    float scale = (g3 < 2) ? 0.5f : 1.0f;
    const float* src = W_hh + ((size_t)i * G_SZ + g3 * 128 + j) * H_SZ + k0;
    __half2 h2 = __floats2half2_rn(scale * src[0], scale * src[1]);
    P[idx] = *reinterpret_cast<uint32_t*>(&h2);
}

// ---------------- transpose x: xT[t][i][b] = x[b][t][i] ----------------
__global__ void xt_kernel(const float* __restrict__ x, float* __restrict__ xT)
{
    int idx = blockIdx.x * blockDim.x + threadIdx.x;
    if (idx >= B_SZ * T_SZ * I_SZ) return;
    int b = idx & 511;
    int r = idx >> 9;
    int i = r & 63;
    int t = r >> 6;
    xT[idx] = x[((size_t)b * T_SZ + t) * I_SZ + i];
}

// ---------------- transpose the 7 [H,H] weight matrices ----------------
__global__ void transpose7_kernel(const float* __restrict__ fp, const float* __restrict__ g1,
                                  const float* __restrict__ g2, const float* __restrict__ wk,
                                  const float* __restrict__ wv, const float* __restrict__ wq,
                                  const float* __restrict__ o0, float* __restrict__ out)
{
    int idx = blockIdx.x * blockDim.x + threadIdx.x;
    if (idx >= 7 * H_SZ * H_SZ) return;
    int w = idx >> 14;
    int r = idx & 16383;
    int k = r >> 7, n = r & 127;
    const float* src = (w == 0) ? fp : (w == 1) ? g1 : (w == 2) ? g2 :
                       (w == 3) ? wk : (w == 4) ? wv : (w == 5) ? wq : o0;
    out[idx] = src[n * 128 + k];
}

// ---------------- adj row dedup (parallel): grid 64 x block 64 ----------------
__global__ void rep_kernel(const float* __restrict__ adj, int* __restrict__ rep)
{
    __shared__ int best;
    const int i = blockIdx.x, j = threadIdx.x;
    if (j == 0) best = i;
    __syncthreads();
    if (j < i) {
        bool eq = true;
        for (int k = 0; k < I_SZ; k++)
            if (adj[i * I_SZ + k] != adj[j * I_SZ + k]) { eq = false; break; }
        if (eq) atomicMin(&best, j);
    }
    __syncthreads();
    if (j == 0) rep[i] = best;
}

// ---------------- GRU scan: R13 (M=32, grid 1024, half2 epilogue) — UNCHANGED ----------------
#define GRU_SMEM_W 98304
#define GRU_SMEM   (GRU_SMEM_W + 2 * 8192)

__global__ __launch_bounds__(256, 2) void gru_kernel(
    const float* __restrict__ xT,     // [T][I][B]
    const uint32_t* __restrict__ P,
    const float* __restrict__ W_ih,   // [I][3H]
    const float* __restrict__ b_ih,
    const float* __restrict__ b_hh,
    float* __restrict__ hs_out)       // [B][I][H]
{
    extern __shared__ char smem[];
    uint4* s_B  = (uint4*)smem;
    uint4* s_A0 = (uint4*)(smem + GRU_SMEM_W);
    uint4* s_A1 = (uint4*)(smem + GRU_SMEM_W + 8192);

    const int i   = blockIdx.y;
    const int b0  = blockIdx.x * 32;
    const int tid = threadIdx.x;
    const int w    = tid >> 5;
    const int lane = tid & 31;
    const int g    = lane >> 2;
    const int t4   = lane & 3;

    {
        const uint4* src = (const uint4*)(P + (size_t)i * 24576);
        for (int idx = tid; idx < 6144; idx += 256) s_B[idx] = src[idx];
    }

    __half2 wr2[2], wz2[2], wn2[2], bin2[2], ccr2[2], ccz2[2], bhn2[2];
#pragma unroll
    for (int q = 0; q < 2; q++) {
        const int j = 16 * w + 8 * q + 2 * t4;
        const int base = i * G_SZ + j;
        wr2[q]  = __floats2half2_rn(0.5f * __ldg(&W_ih[base]),       0.5f * __ldg(&W_ih[base + 1]));
        wz2[q]  = __floats2half2_rn(0.5f * __ldg(&W_ih[base + 128]), 0.5f * __ldg(&W_ih[base + 129]));
        wn2[q]  = __floats2half2_rn(__ldg(&W_ih[base + 256]),        __ldg(&W_ih[base + 257]));
        ccr2[q] = __floats2half2_rn(0.5f * (__ldg(&b_ih[base])       + __ldg(&b_hh[base])),
                                    0.5f * (__ldg(&b_ih[base + 1])   + __ldg(&b_hh[base + 1])));
        ccz2[q] = __floats2half2_rn(0.5f * (__ldg(&b_ih[base + 128]) + __ldg(&b_hh[base + 128])),
                                    0.5f * (__ldg(&b_ih[base + 129]) + __ldg(&b_hh[base + 129])));
        bin2[q] = __floats2half2_rn(__ldg(&b_ih[base + 256]), __ldg(&b_ih[base + 257]));
        bhn2[q] = __floats2half2_rn(__ldg(&b_hh[base + 256]), __ldg(&b_hh[base + 257]));
    }

    __half2 hq[2][2][2];
    const __half2 hhalf = __float2half2_rn(0.5f);
#pragma unroll
    for (int mt = 0; mt < 2; mt++)
#pragma unroll
        for (int q = 0; q < 2; q++)
            hq[mt][q][0] = hq[mt][q][1] = __float2half2_rn(0.0f);

    __syncthreads();

    const float* xrow = xT + (size_t)i * B_SZ + b0;

    for (int t = 0; t < T_SZ; t++) {
        uint4* sA = (t & 1) ? s_A1 : s_A0;

        if (t > 0) {
#pragma unroll
            for (int mt = 0; mt < 2; mt++) {
                uint4 v;
                v.x = *reinterpret_cast<uint32_t*>(&hq[mt][0][0]);
                v.y = *reinterpret_cast<uint32_t*>(&hq[mt][0][1]);
                v.z = *reinterpret_cast<uint32_t*>(&hq[mt][1][0]);
                v.w = *reinterpret_cast<uint32_t*>(&hq[mt][1][1]);
                sA[(w * 2 + mt) * 32 + lane] = v;
            }
        }
        __syncthreads();

        __half2 x2[2][2];
#pragma unroll
        for (int mt = 0; mt < 2; mt++)
#pragma unroll
            for (int hi = 0; hi < 2; hi++)
                x2[mt][hi] = __float2half2_rn(__ldg(xrow + 16 * mt + g + 8 * hi));
        xrow += I_SZ * B_SZ;

        float D[2][6][4];
#pragma unroll
        for (int mt = 0; mt < 2; mt++)
#pragma unroll
            for (int n = 0; n < 6; n++)
#pragma unroll
                for (int c = 0; c < 4; c++) D[mt][n][c] = 0.0f;

        if (t > 0) {
#pragma unroll
            for (int kt = 0; kt < 8; kt++) {
                uint4 a0 = sA[(kt * 2 + 0) * 32 + lane];
                uint4 a1 = sA[(kt * 2 + 1) * 32 + lane];
                uint32_t af0[4] = {a0.x, a0.y, a0.z, a0.w};
                uint32_t af1[4] = {a1.x, a1.y, a1.z, a1.w};
#pragma unroll
                for (int g3 = 0; g3 < 3; g3++) {
                    uint4 bv = s_B[((w * 3 + g3) * 8 + kt) * 32 + lane];
                    mma_f16(D[0][2 * g3 + 0], af0, bv.x, bv.y);
                    mma_f16(D[0][2 * g3 + 1], af0, bv.z, bv.w);
                    mma_f16(D[1][2 * g3 + 0], af1, bv.x, bv.y);
                    mma_f16(D[1][2 * g3 + 1], af1, bv.z, bv.w);
                }
            }
        }

#pragma unroll
        for (int mt = 0; mt < 2; mt++) {
#pragma unroll
            for (int hi = 0; hi < 2; hi++) {
                const __half2 xt2 = x2[mt][hi];
                const int c0 = 2 * hi, c1 = 2 * hi + 1;
#pragma unroll
                for (int q = 0; q < 2; q++) {
                    __half2 ur2 = __hadd2(cvt2(D[mt][q][c0], D[mt][q][c1]), ccr2[q]);
                    ur2 = __hfma2(xt2, wr2[q], ur2);
                    const __half2 r2 = __hfma2(tanh2(ur2), hhalf, hhalf);
                    __half2 uz2 = __hadd2(cvt2(D[mt][2 + q][c0], D[mt][2 + q][c1]), ccz2[q]);
                    uz2 = __hfma2(xt2, wz2[q], uz2);
                    const __half2 z2 = __hfma2(tanh2(uz2), hhalf, hhalf);
                    const __half2 inn2 = __hfma2(xt2, wn2[q], bin2[q]);
                    const __half2 hn2  = __hadd2(cvt2(D[mt][4 + q][c0], D[mt][4 + q][c1]), bhn2[q]);
                    const __half2 th2  = tanh2(__hfma2(r2, hn2, inn2));
                    const __half2 hold = hq[mt][q][hi];
                    hq[mt][q][hi] = __hfma2(z2, __hsub2(hold, th2), th2);
                }
            }
        }
    }

#pragma unroll
    for (int mt = 0; mt < 2; mt++)
#pragma unroll
        for (int q = 0; q < 2; q++) {
            const int j = 16 * w + 8 * q + 2 * t4;
#pragma unroll
            for (int hi = 0; hi < 2; hi++) {
                const int b = b0 + 16 * mt + g + 8 * hi;
                float2 f = __half22float2(hq[mt][q][hi]);
                *(float2*)(hs_out + ((size_t)b * I_SZ + i) * H_SZ + j) = f;
            }
        }
}

// ---------------- tail: full ht linear (warp-tiled, unchanged numerics) ----------------
__device__ __forceinline__ void lin_smem(const float* __restrict__ Xin, const float* __restrict__ Wt,
                                         const float* __restrict__ bias, float* __restrict__ Yout,
                                         float* __restrict__ gout, int relu, int w, int l)
{
    const int r0 = w * 8;
    float acc[8][4];
#pragma unroll
    for (int rr = 0; rr < 8; rr++)
#pragma unroll
        for (int c = 0; c < 4; c++) acc[rr][c] = 0.f;
#pragma unroll 4
    for (int k = 0; k < 128; k++) {
        float wv[4];
#pragma unroll
        for (int c = 0; c < 4; c++) wv[c] = __ldg(&Wt[k * 128 + l + 32 * c]);
#pragma unroll
        for (int rr = 0; rr < 8; rr++) {
            const float xv = Xin[(r0 + rr) * 128 + k];
#pragma unroll
            for (int c = 0; c < 4; c++) acc[rr][c] = fmaf(xv, wv[c], acc[rr][c]);
        }
    }
#pragma unroll
    for (int rr = 0; rr < 8; rr++)
#pragma unroll
        for (int c = 0; c < 4; c++) {
            const int n = l + 32 * c;
            float v = acc[rr][c] + __ldg(&bias[n]);
            if (relu) v = fmaxf(v, 0.f);
            Yout[(r0 + rr) * 128 + n] = v;
            if (gout) gout[(size_t)(r0 + rr) * 128 + n] = v;
        }
}

// compact linear: nU rows only. items = nU*128.
__device__ __forceinline__ void lin_compact(const float* __restrict__ Xin, const float* __restrict__ Wt,
                                            const float* __restrict__ bias, float* __restrict__ Yout,
                                            int nU, int tid)
{
    const int total = nU * 128;
    for (int item = tid; item < total; item += 256) {
        const int u = item >> 7, col = item & 127;
        float acc = __ldg(&bias[col]);
        const float* xr = Xin + u * 128;
#pragma unroll 4
        for (int k = 0; k < 128; k++)
            acc = fmaf(xr[k], __ldg(&Wt[k * 128 + col]), acc);
        Yout[u * 128 + col] = fmaxf(acc, 0.f);
    }
}

// one block per batch: hs -> ht(out) -> [dedup graph-conv chain on nU rows] -> attention -> out
#define TAIL_SMEM ((8192 + 8192 + 4096 + 512 + 80) * 4)

__global__ __launch_bounds__(256) void tail_kernel(
    const float* __restrict__ hs, const float* __restrict__ adj, const int* __restrict__ rep,
    const float* __restrict__ fpT, const float* __restrict__ fp_b,
    const float* __restrict__ g1T, const float* __restrict__ g1_b,
    const float* __restrict__ g2T, const float* __restrict__ g2_b,
    const float* __restrict__ wqT, const float* __restrict__ wq_b,
    const float* __restrict__ wk_w, const float* __restrict__ wk_b,
    const float* __restrict__ wvT, const float* __restrict__ wv_b,
    const float* __restrict__ o0T, const float* __restrict__ o0_b,
    float* __restrict__ ht_out, float* __restrict__ out)
{
    extern __shared__ float sm[];
    float* Xs   = sm;                   // [64][128] (hs, then Z1u/Z2u compact)
    float* Zs   = sm + 8192;            // [64][128] (ht, then G1u/ctxu compact)
    float* Su   = sm + 16384;           // [64][64] worst case
    float* q    = sm + 20480;
    float* uvec = q + 128;
    float* sv   = uvec + 128;
    float* wc   = sv + 128;
    float* ev   = wc + 128;
    float* red  = ev + 64;              // [2]
    __shared__ int srep[64], ulist[64], uidx[64];
    __shared__ float cntf[64];
    __shared__ int nU_s;

    const int b = blockIdx.x;
    const int tid = threadIdx.x, w = tid >> 5, l = tid & 31;

    for (int idx = tid; idx < 8192; idx += 256)
        Xs[idx] = hs[(size_t)b * 8192 + idx];
    if (tid < 64) srep[tid] = rep[tid];
    __syncthreads();
    if (tid == 0) {
        int n = 0;
        for (int r = 0; r < 64; r++) {
            if (srep[r] == r) { ulist[n] = r; uidx[r] = n; cntf[n] = 0.f; n++; }
        }
        for (int r = 0; r < 64; r++) {
            const int u = uidx[srep[r]];
            uidx[r] = u;
            cntf[u] += 1.0f;
        }
        nU_s = n;
    }
    __syncthreads();
    const int nU = nU_s;

    // 1) ht = hs @ fpT + fp_b -> Zs (full 64 rows; also to d_out)
    lin_smem(Xs, fpT, fp_b, Zs, ht_out + (size_t)b * 8192, 0, w, l);
    __syncthreads();

    // 2) Su[u][v] = sum_j adj[ulist[u]][j] * [rep[j] == ulist[v]]
    for (int item = tid; item < nU * nU; item += 256) {
        const int u = item / nU, v = item % nU;
        const int row = ulist[u];
        float acc = 0.f;
        for (int j = 0; j < 64; j++)
            if (uidx[j] == v) acc += __ldg(&adj[row * 64 + j]);
        Su[u * 64 + v] = acc;
    }
    // 3) Z1u[u] = sum_j adj[ulist[u]][j] * ht[j]  -> Xs compact
    {
        const int total = nU * 128;
        for (int item = tid; item < total; item += 256) {
            const int u = item >> 7, col = item & 127;
            const int row = ulist[u];
            float acc = 0.f;
#pragma unroll 4
            for (int j = 0; j < 64; j++)
                acc = fmaf(__ldg(&adj[row * 64 + j]), Zs[j * 128 + col], acc);
            Xs[u * 128 + col] = acc;
        }
    }
    __syncthreads();

    // 4) G1u = relu(Z1u @ g1T + b1) -> Zs compact
    lin_compact(Xs, g1T, g1_b, Zs, nU, tid);
    __syncthreads();

    // 5) Z2u[u] = sum_v Su[u][v] * G1u[v] -> Xs compact
    {
        const int total = nU * 128;
        for (int item = tid; item < total; item += 256) {
            const int u = item >> 7, col = item & 127;
            float acc = 0.f;
            for (int v = 0; v < nU; v++)
                acc = fmaf(Su[u * 64 + v], Zs[v * 128 + col], acc);
            Xs[u * 128 + col] = acc;
        }
    }
    __syncthreads();

    // 6) ctxu = relu(Z2u @ g2T + b2) -> Zs compact
    lin_compact(Xs, g2T, g2_b, Zs, nU, tid);
    __syncthreads();

    // ---- attention on compact ctx ----
    const int u63 = uidx[63];
    if (tid < 128) {
        float acc = __ldg(&wq_b[tid]);
        const float* cr = Zs + u63 * 128;
        for (int k = 0; k < 128; k++)
            acc = fmaf(cr[k], __ldg(&wqT[k * 128 + tid]), acc);
        q[tid] = acc;
    }
    __syncthreads();
    if (tid < 128) {
        float acc = 0.f;
        for (int n = 0; n < 128; n++)
            acc = fmaf(q[n], __ldg(&wk_w[n * 128 + tid]), acc);
        uvec[tid] = acc;
    }
    if (tid == 128) {
        float c = 0.f;
        for (int n = 0; n < 128; n++) c = fmaf(q[n], __ldg(&wk_b[n]), c);
        red[0] = c;
    }
    __syncthreads();
    if (tid < nU) {
        float e = red[0];
        const float* cr = Zs + tid * 128;
        for (int k = 0; k < 128; k++) e = fmaf(cr[k], uvec[k], e);
        ev[tid] = e;
    }
    __syncthreads();
    if (tid == 0) {
        float mx = -1e30f;
        for (int u = 0; u < nU; u++) mx = fmaxf(mx, ev[u]);
        float den = 0.f;
        for (int u = 0; u < nU; u++) den += cntf[u] * __expf(ev[u] - mx);
        red[0] = mx; red[1] = 1.0f / den;
    }
    __syncthreads();
    if (tid < nU) ev[tid] = cntf[tid] * __expf(ev[tid] - red[0]) * red[1];
    __syncthreads();
    if (tid < 128) {
        float acc = 0.f;
        for (int u = 0; u < nU; u++) acc = fmaf(ev[u], Zs[u * 128 + tid], acc);
        sv[tid] = acc;
    }
    __syncthreads();
    if (tid < 128) {
        float acc = __ldg(&wv_b[tid]);
        for (int k = 0; k < 128; k++) acc = fmaf(sv[k], __ldg(&wvT[k * 128 + tid]), acc);
        wc[tid] = acc;
    }
    __syncthreads();
    if (tid < 128) {
        float acc = __ldg(&o0_b[tid]);
        for (int m = 0; m < 128; m++) acc = fmaf(wc[m], __ldg(&o0T[m * 128 + tid]), acc);
        out[(size_t)b * 128 + tid] = fmaxf(acc, 0.f);
    }
}

// ---------------- launch ----------------
extern "C" void kernel_launch(void* const* d_in, const int* in_sizes, int n_in,
                              void* d_out, int out_size)
{
    const float* x     = (const float*)d_in[0];
    const float* W_ih  = (const float*)d_in[1];
    const float* W_hh  = (const float*)d_in[2];
    const float* b_ih  = (const float*)d_in[3];
    const float* b_hh  = (const float*)d_in[4];
    const float* fp_w  = (const float*)d_in[5];
    const float* fp_b  = (const float*)d_in[6];
    const float* g1_w  = (const float*)d_in[7];
    const float* g1_b  = (const float*)d_in[8];
    const float* g2_w  = (const float*)d_in[9];
    const float* g2_b  = (const float*)d_in[10];
    const float* wq_w  = (const float*)d_in[11];
    const float* wq_b  = (const float*)d_in[12];
    const float* wk_w  = (const float*)d_in[13];
    const float* wk_b  = (const float*)d_in[14];
    const float* wv_w  = (const float*)d_in[15];
    const float* wv_b  = (const float*)d_in[16];
    const float* o0_w  = (const float*)d_in[17];
    const float* o0_b  = (const float*)d_in[18];
    const float* adj   = (const float*)d_in[19];

    float* out = (float*)d_out;
    float* ht_out = out + B_SZ * H_SZ;

    uint32_t* P;
    float *hs, *A, *Wt;
    int* rep;
    cudaGetSymbolAddress((void**)&P,  g_P);
    cudaGetSymbolAddress((void**)&hs, g_hs);
    cudaGetSymbolAddress((void**)&A,  g_A);
    cudaGetSymbolAddress((void**)&Wt, g_Wt);
    cudaGetSymbolAddress((void**)&rep, g_rep);

    cudaFuncSetAttribute(gru_kernel, cudaFuncAttributeMaxDynamicSharedMemorySize, GRU_SMEM);
    cudaFuncSetAttribute(tail_kernel, cudaFuncAttributeMaxDynamicSharedMemorySize, TAIL_SMEM);

    // prep
    pack_whh_kernel<<<(I_SZ * 24576 + 255) / 256, 256>>>(W_hh, P);
    transpose7_kernel<<<(7 * H_SZ * H_SZ + 255) / 256, 256>>>(fp_w, g1_w, g2_w, wk_w, wv_w, wq_w, o0_w, Wt);
    xt_kernel<<<(B_SZ * T_SZ * I_SZ + 255) / 256, 256>>>(x, A);
    rep_kernel<<<64, 64>>>(adj, rep);

    const float* fpT = Wt + 0 * 16384;
    const float* g1T = Wt + 1 * 16384;
    const float* g2T = Wt + 2 * 16384;
    const float* wvT = Wt + 4 * 16384;
    const float* wqT = Wt + 5 * 16384;
    const float* o0T = Wt + 6 * 16384;

    // 1) GRU scan -> hs (M=32 per CTA, 1024 CTAs)
    gru_kernel<<<dim3(16, 64), 256, GRU_SMEM>>>(A, P, W_ih, b_ih, b_hh, hs);

    // 2) fused tail (dedup-collapsed graph convs)
    tail_kernel<<<B_SZ, 256, TAIL_SMEM>>>(hs, adj, rep,
                                          fpT, fp_b, g1T, g1_b, g2T, g2_b,
                                          wqT, wq_b, wk_w, wk_b, wvT, wv_b,
                                          o0T, o0_b, ht_out, out);
}